// round 2
// baseline (speedup 1.0000x reference)
#include <cuda_runtime.h>
#include <math.h>

// ---------------- problem constants ----------------
#define LROW   8192
#define LMASK  8191
#define CC     64
#define NT     512         // threads per fused block
#define TLP    128         // output tile length
#define NY     144         // Prim/y tile: t in [-8, TL+8), offset +8
#define N1     140         // h1 points:   t in [-6, TL+6), offset +6
#define N2     136         // h2 points:   t in [-4, TL+4), offset +4
#define N3     132         // coeffs/grad: t in [-2, TL+2), offset +2
#define DXC    0.015625f   // 1/64
#define INVDX  64.0f
#define CFLC   0.01f

// ---------------- smem layout (float offsets) ----------------
#define OFF_PRIM 0           // 144
#define OFF_Y    144         // 144
#define OFF_W1   288         // 5*64 = 320
#define OFF_B1   608         // 64
#define OFF_B2   672         // 64
#define OFF_B3   736         // 4 (pad 8)
#define OFF_W3   744         // 5*64*4 = 1280
#define OFF_GRAD 2024        // 132 (pad 136)
#define OFF_COEF 2160        // 132*4 = 528
#define OFF_W2   2688        // 5*64*64 = 20480
#define OFF_H1   23168       // 140*64 = 8960
#define OFF_H2   32128       // 136*64 = 8704
#define SMEM_FLOATS 40832    // 163,328 bytes

// ---------------- scratch for per-row min/max ----------------
__device__ float g_mn[2048];
__device__ float g_mx[2048];

// ---------------- static polynomial-accuracy constants ----------------
// alpha_p = solve(vandermonde([-2..2]), e1') = [1/12, -2/3, 0, 2/3, -1/12]
__constant__ float c_alpha_p[5] = {
    0.083333333333333329f, -0.66666666666666663f, 0.0f,
    0.66666666666666663f, -0.083333333333333329f};
// NULL_BASIS = rows 1..4 of Vh from np.linalg.svd([[1,1,1,1,1]])
// (LAPACK Householder completion: col0 = -1/sqrt(5); diag 1-1/(5+sqrt5); off -1/(5+sqrt5))
__constant__ float c_nb[4][5] = {
 {-0.44721359549995793f,  0.86180339887498949f, -0.13819660112501051f, -0.13819660112501051f, -0.13819660112501051f},
 {-0.44721359549995793f, -0.13819660112501051f,  0.86180339887498949f, -0.13819660112501051f, -0.13819660112501051f},
 {-0.44721359549995793f, -0.13819660112501051f, -0.13819660112501051f,  0.86180339887498949f, -0.13819660112501051f},
 {-0.44721359549995793f, -0.13819660112501051f, -0.13819660112501051f, -0.13819660112501051f,  0.86180339887498949f}};

// ================= per-row min/max =================
__global__ void row_minmax(const float* __restrict__ x) {
    int row = blockIdx.x;
    const float4* p = (const float4*)(x + (size_t)row * LROW);
    float mn = INFINITY, mx = -INFINITY;
    for (int i = threadIdx.x; i < LROW / 4; i += blockDim.x) {
        float4 v = p[i];
        mn = fminf(mn, fminf(fminf(v.x, v.y), fminf(v.z, v.w)));
        mx = fmaxf(mx, fmaxf(fmaxf(v.x, v.y), fmaxf(v.z, v.w)));
    }
    #pragma unroll
    for (int off = 16; off; off >>= 1) {
        mn = fminf(mn, __shfl_xor_sync(0xffffffffu, mn, off));
        mx = fmaxf(mx, __shfl_xor_sync(0xffffffffu, mx, off));
    }
    __shared__ float smn[32], smx[32];
    int w = threadIdx.x >> 5, l = threadIdx.x & 31;
    if (l == 0) { smn[w] = mn; smx[w] = mx; }
    __syncthreads();
    if (threadIdx.x < 32) {
        int nw = blockDim.x >> 5;
        mn = (l < nw) ? smn[l] : INFINITY;
        mx = (l < nw) ? smx[l] : -INFINITY;
        #pragma unroll
        for (int off = 16; off; off >>= 1) {
            mn = fminf(mn, __shfl_xor_sync(0xffffffffu, mn, off));
            mx = fmaxf(mx, __shfl_xor_sync(0xffffffffu, mx, off));
        }
        if (l == 0) { g_mn[row] = mn; g_mx[row] = mx; }
    }
}

// ================= fused model kernel =================
__device__ __forceinline__ float phi_fn(float gp, float g) {
    float aa = (g < 0.f) ? -1.f : 1.f;             // min(sign(g),0)*2+1
    float ri = gp / (fmaxf(fabsf(g), 1e-15f) * aa);
    return (ri * ri + ri) / (ri * ri + 1.f);
}

__global__ __launch_bounds__(NT) void fused_kernel(
    const float* __restrict__ Prim,
    const float* __restrict__ W1, const float* __restrict__ B1,
    const float* __restrict__ W2, const float* __restrict__ B2,
    const float* __restrict__ W3, const float* __restrict__ B3,
    float* __restrict__ Out)
{
    extern __shared__ float sm[];
    const int tid = threadIdx.x;
    const int row = blockIdx.y;
    const int i0  = blockIdx.x * TLP;
    const float* prow = Prim + (size_t)row * LROW;

    // ---- cooperative weight loads into smem ----
    {
        const float4* s = (const float4*)W2; float4* d = (float4*)(sm + OFF_W2);
        for (int i = tid; i < 5 * 64 * 64 / 4; i += NT) d[i] = s[i];
    }
    {
        const float4* s = (const float4*)W1; float4* d = (float4*)(sm + OFF_W1);
        for (int i = tid; i < 5 * 64 / 4; i += NT) d[i] = s[i];
    }
    {
        const float4* s = (const float4*)W3; float4* d = (float4*)(sm + OFF_W3);
        for (int i = tid; i < 5 * 64 * 4 / 4; i += NT) d[i] = s[i];
    }
    if (tid < 64) { sm[OFF_B1 + tid] = B1[tid]; sm[OFF_B2 + tid] = B2[tid]; }
    if (tid < 4)  { sm[OFF_B3 + tid] = B3[tid]; }

    // ---- Prim tile + rescale-to-range ----
    float mn = g_mn[row], mx = g_mx[row];
    float inv = 1.0f / fmaxf((mx - mn) * 0.5f, 1e-4f);
    if (tid < NY) {
        float v = prow[(i0 + tid - 8) & LMASK];
        sm[OFF_PRIM + tid] = v;
        sm[OFF_Y + tid]    = (v - mn) * inv - 1.0f;
    }
    __syncthreads();

    // ---- conv1 + tanh : h1[p][c], p in [0, N1) ----
    {
        int c = tid & 63;
        for (int p = tid >> 6; p < N1; p += 8) {
            float acc = sm[OFF_B1 + c];
            #pragma unroll
            for (int k = 0; k < 5; k++)
                acc += sm[OFF_W1 + k * 64 + c] * sm[OFF_Y + p + k];
            sm[OFF_H1 + p * 64 + c] = tanhf(acc);
        }
    }
    __syncthreads();

    // ---- conv2 + tanh : the hot loop (register-blocked, 17 pts/thread) ----
    {
        const int c  = tid & 63;
        const int p0 = (tid >> 6) * 17;       // 8 subs * 17 = 136 = N2 exactly
        float acc[17];
        const float bb = sm[OFF_B2 + c];
        #pragma unroll
        for (int j = 0; j < 17; j++) acc[j] = bb;
        #pragma unroll 1
        for (int k = 0; k < 5; k++) {
            const float* wk = sm + OFF_W2 + k * 4096 + c;   // [ci][c], coalesced over lanes
            const float* hk = sm + OFF_H1 + (p0 + k) * 64;  // broadcast over lanes
            #pragma unroll 2
            for (int ci = 0; ci < 64; ci += 4) {
                float w0 = wk[(ci + 0) * 64];
                float w1 = wk[(ci + 1) * 64];
                float w2 = wk[(ci + 2) * 64];
                float w3 = wk[(ci + 3) * 64];
                #pragma unroll
                for (int j = 0; j < 17; j++) {
                    float4 h = *(const float4*)(hk + j * 64 + ci);
                    acc[j] += w0 * h.x;
                    acc[j] += w1 * h.y;
                    acc[j] += w2 * h.z;
                    acc[j] += w3 * h.w;
                }
            }
        }
        #pragma unroll
        for (int j = 0; j < 17; j++)
            sm[OFF_H2 + (p0 + j) * 64 + c] = tanhf(acc[j]);
    }
    __syncthreads();

    // ---- conv3 : coeffs[p][o], p in [0, N3) ----
    {
        int o = tid & 3;
        int p = tid >> 2;               // 0..127
        for (int pp = p; pp < N3; pp += 128) {
            float acc = sm[OFF_B3 + o];
            #pragma unroll 1
            for (int k = 0; k < 5; k++) {
                const float* wk = sm + OFF_W3 + k * 256 + o;
                const float* hk = sm + OFF_H2 + (pp + k) * 64;
                #pragma unroll 4
                for (int ci = 0; ci < 64; ci += 4) {
                    float4 h = *(const float4*)(hk + ci);
                    acc += wk[(ci + 0) * 4] * h.x;
                    acc += wk[(ci + 1) * 4] * h.y;
                    acc += wk[(ci + 2) * 4] * h.z;
                    acc += wk[(ci + 3) * 4] * h.w;
                }
            }
            sm[OFF_COEF + pp * 4 + o] = acc;
        }
    }
    __syncthreads();

    // ---- alpha + grad_x ----
    if (tid < N3) {
        int p = tid;
        float co0 = sm[OFF_COEF + p * 4 + 0];
        float co1 = sm[OFF_COEF + p * 4 + 1];
        float co2 = sm[OFF_COEF + p * 4 + 2];
        float co3 = sm[OFF_COEF + p * 4 + 3];
        float g = 0.f;
        #pragma unroll
        for (int k = 0; k < 5; k++) {
            float a = c_alpha_p[k] + co0 * c_nb[0][k] + co1 * c_nb[1][k]
                                   + co2 * c_nb[2][k] + co3 * c_nb[3][k];
            g += a * sm[OFF_PRIM + p + 4 + k];   // Prim[t+k-2], t = p-2
        }
        sm[OFF_GRAD + p] = g * INVDX;
    }
    __syncthreads();

    // ---- TVD limiter + Godunov flux + update ----
    if (tid < TLP) {
        int t = tid;
        float g_m2 = sm[OFF_GRAD + t + 0];
        float g_m1 = sm[OFF_GRAD + t + 1];
        float g_0  = sm[OFF_GRAD + t + 2];
        float g_p1 = sm[OFF_GRAD + t + 3];
        float P_m1 = sm[OFF_PRIM + t + 7];
        float P_0  = sm[OFF_PRIM + t + 8];
        float P_p1 = sm[OFF_PRIM + t + 9];

        float phim = phi_fn(g_m2, g_m1);
        float phi0 = phi_fn(g_m1, g_0);
        float phip = phi_fn(g_0,  g_p1);

        float uL1 = P_0  + 0.5f * DXC * phi0 * g_0;
        float uR1 = P_p1 - 0.5f * DXC * phip * g_p1;
        float f1  = 0.25f * (uL1 * uL1 + uR1 * uR1)
                  - 0.25f * fabsf(uL1 + uR1) * (uR1 - uL1);

        float uL0 = P_m1 + 0.5f * DXC * phim * g_m1;
        float uR0 = P_0  - 0.5f * DXC * phi0 * g_0;
        float f0  = 0.25f * (uL0 * uL0 + uR0 * uR0)
                  - 0.25f * fabsf(uL0 + uR0) * (uR0 - uL0);

        Out[(size_t)row * LROW + i0 + t] = P_0 - CFLC * (f1 - f0);
    }
}

// ================= launch =================
extern "C" void kernel_launch(void* const* d_in, const int* in_sizes, int n_in,
                              void* d_out, int out_size) {
    const float* Prim = (const float*)d_in[0];
    const float* W1   = (const float*)d_in[1];
    const float* B1   = (const float*)d_in[2];
    const float* W2   = (const float*)d_in[3];
    const float* B2   = (const float*)d_in[4];
    const float* W3   = (const float*)d_in[5];
    const float* B3   = (const float*)d_in[6];
    int Brows = in_sizes[0] / LROW;

    row_minmax<<<Brows, 256>>>(Prim);

    size_t smem = SMEM_FLOATS * sizeof(float);
    cudaFuncSetAttribute(fused_kernel,
                         cudaFuncAttributeMaxDynamicSharedMemorySize, (int)smem);
    fused_kernel<<<dim3(LROW / TLP, Brows), NT, smem>>>(
        Prim, W1, B1, W2, B2, W3, B3, (float*)d_out);
}

// round 5
// speedup vs baseline: 8.3561x; 8.3561x over previous
#include <cuda_runtime.h>
#include <cuda_bf16.h>
#include <stdint.h>
#include <math.h>

// Round 5 = Round 3 kernel resubmitted verbatim after infra failure
// ("GB300 container failed twice"); offline audit found no correctness issue.

// ---------------- problem constants ----------------
#define LROW   8192
#define LMASK  8191
#define NT     512
#define TLP    120          // output points per tile
#define NTILE  69           // ceil(8192/120)
#define NY     136          // Prim/y halo, offset +8
#define N1     132          // h1 points (buf idx j = gridpoint-i0+6)
#define DXC    0.015625f
#define INVDX  64.0f
#define CFLC   0.01f

// padded strides (bytes): conflict-free for ldmatrix (shift 4 banks/row)
#define H_STRIDE  144       // 64ch bf16 = 128B + 16 pad
#define W_STRIDE  656       // 320 bf16 = 640B + 16 pad

// dynamic smem layout (bytes)
#define OFF_W2  0                        // 64 * 656 = 41984
#define OFF_W3  41984                    // 8 * 656  = 5248
#define OFF_H1  47232                    // 136 * 144 = 19584
#define OFF_H2  66816                    // 136 * 144 = 19584
#define DYN_BYTES 86400

// ---------------- device globals ----------------
__device__ float g_mn[2048], g_mx[2048];
__device__ __align__(16) __nv_bfloat16 g_W2t[64 * 328];  // [ch][K=320 pad 328]
__device__ __align__(16) __nv_bfloat16 g_W3t[8 * 328];   // rows 4..7 zero

__constant__ float c_alpha_p[5] = {
    0.083333333333333329f, -0.66666666666666663f, 0.0f,
    0.66666666666666663f, -0.083333333333333329f};
__constant__ float c_nb[4][5] = {
 {-0.44721359549995793f,  0.86180339887498949f, -0.13819660112501051f, -0.13819660112501051f, -0.13819660112501051f},
 {-0.44721359549995793f, -0.13819660112501051f,  0.86180339887498949f, -0.13819660112501051f, -0.13819660112501051f},
 {-0.44721359549995793f, -0.13819660112501051f, -0.13819660112501051f,  0.86180339887498949f, -0.13819660112501051f},
 {-0.44721359549995793f, -0.13819660112501051f, -0.13819660112501051f, -0.13819660112501051f,  0.86180339887498949f}};

// ---------------- helpers ----------------
__device__ __forceinline__ uint32_t smem_u32(const void* p) {
    uint32_t a;
    asm("{ .reg .u64 t; cvta.to.shared.u64 t, %1; cvt.u32.u64 %0, t; }" : "=r"(a) : "l"(p));
    return a;
}
__device__ __forceinline__ float tanh_ap(float x) {
    float y; asm("tanh.approx.f32 %0, %1;" : "=f"(y) : "f"(x)); return y;
}
__device__ __forceinline__ uint32_t pack_bf16x2(float lo, float hi) {
    uint32_t d;
    asm("cvt.rn.bf16x2.f32 %0, %1, %2;" : "=r"(d) : "f"(hi), "f"(lo));
    return d;
}
__device__ __forceinline__ void ldsm4(uint32_t* r, uint32_t addr) {
    asm volatile("ldmatrix.sync.aligned.m8n8.x4.shared.b16 {%0,%1,%2,%3}, [%4];"
        : "=r"(r[0]), "=r"(r[1]), "=r"(r[2]), "=r"(r[3]) : "r"(addr));
}
__device__ __forceinline__ void ldsm2(uint32_t* r, uint32_t addr) {
    asm volatile("ldmatrix.sync.aligned.m8n8.x2.shared.b16 {%0,%1}, [%2];"
        : "=r"(r[0]), "=r"(r[1]) : "r"(addr));
}
__device__ __forceinline__ void mma16816(float* d, const uint32_t* a, const uint32_t* b) {
    asm volatile("mma.sync.aligned.m16n8k16.row.col.f32.bf16.bf16.f32 "
        "{%0,%1,%2,%3}, {%4,%5,%6,%7}, {%8,%9}, {%0,%1,%2,%3};"
        : "+f"(d[0]), "+f"(d[1]), "+f"(d[2]), "+f"(d[3])
        : "r"(a[0]), "r"(a[1]), "r"(a[2]), "r"(a[3]), "r"(b[0]), "r"(b[1]));
}

// ================= weight prep: fp32 -> bf16 padded row-major =================
__global__ void prep_weights(const float* __restrict__ W2, const float* __restrict__ W3) {
    int tid = threadIdx.x;
    for (int i = tid; i < 8 * 328; i += NT) g_W3t[i] = __float2bfloat16(0.f);
    __syncthreads();
    // W2 [k][ci][c] -> g_W2t[c][k*64+ci]
    for (int i = tid; i < 5 * 64 * 64; i += NT) {
        int k = i >> 12, ci = (i >> 6) & 63, c = i & 63;
        g_W2t[c * 328 + k * 64 + ci] = __float2bfloat16(W2[i]);
    }
    // W3 [k][ci][o] -> g_W3t[o][k*64+ci]
    for (int i = tid; i < 5 * 64 * 4; i += NT) {
        int k = i >> 8, ci = (i >> 2) & 63, o = i & 3;
        g_W3t[o * 328 + k * 64 + ci] = __float2bfloat16(W3[i]);
    }
}

// ================= per-row min/max =================
__global__ void row_minmax(const float* __restrict__ x) {
    int row = blockIdx.x;
    const float4* p = (const float4*)(x + (size_t)row * LROW);
    float mn = INFINITY, mx = -INFINITY;
    for (int i = threadIdx.x; i < LROW / 4; i += blockDim.x) {
        float4 v = p[i];
        mn = fminf(mn, fminf(fminf(v.x, v.y), fminf(v.z, v.w)));
        mx = fmaxf(mx, fmaxf(fmaxf(v.x, v.y), fmaxf(v.z, v.w)));
    }
    #pragma unroll
    for (int off = 16; off; off >>= 1) {
        mn = fminf(mn, __shfl_xor_sync(0xffffffffu, mn, off));
        mx = fmaxf(mx, __shfl_xor_sync(0xffffffffu, mx, off));
    }
    __shared__ float smn[8], smx[8];
    int w = threadIdx.x >> 5, l = threadIdx.x & 31;
    if (l == 0) { smn[w] = mn; smx[w] = mx; }
    __syncthreads();
    if (threadIdx.x < 32) {
        mn = (l < 8) ? smn[l] : INFINITY;
        mx = (l < 8) ? smx[l] : -INFINITY;
        #pragma unroll
        for (int off = 4; off; off >>= 1) {
            mn = fminf(mn, __shfl_xor_sync(0xffffffffu, mn, off));
            mx = fmaxf(mx, __shfl_xor_sync(0xffffffffu, mx, off));
        }
        if (l == 0) { g_mn[row] = mn; g_mx[row] = mx; }
    }
}

// ================= fused tile kernel =================
__device__ __forceinline__ float phi_fn(float gp, float g) {
    float aa = (g < 0.f) ? -1.f : 1.f;
    float ri = gp / (fmaxf(fabsf(g), 1e-15f) * aa);
    return (ri * ri + ri) / (ri * ri + 1.f);
}

__global__ void __launch_bounds__(NT, 2) fused_kernel(
    const float* __restrict__ Prim,
    const float* __restrict__ W1, const float* __restrict__ B1,
    const float* __restrict__ B2, const float* __restrict__ B3,
    float* __restrict__ Out)
{
    __shared__ float sPrim[NY], sY[NY];
    __shared__ float sW1[320], sB1[64], sB2[64], sB3[4];
    __shared__ float sGrad[128];
    __shared__ float sCoef[128 * 4];
    extern __shared__ unsigned char dyn[];

    const int tid = threadIdx.x;
    const int w   = tid >> 5;
    const int l   = tid & 31;
    const int row = blockIdx.y;
    const int i0  = blockIdx.x * TLP;

    const uint32_t dbase = smem_u32(dyn);
    const uint32_t aW2 = dbase + OFF_W2;
    const uint32_t aW3 = dbase + OFF_W3;
    const uint32_t aH1 = dbase + OFF_H1;
    const uint32_t aH2 = dbase + OFF_H2;

    // ---- weights: global bf16 -> smem (uint4) ----
    {
        const uint4* s = (const uint4*)g_W2t; uint4* d = (uint4*)(dyn + OFF_W2);
        for (int i = tid; i < 64 * 656 / 16; i += NT) d[i] = s[i];
        const uint4* s2 = (const uint4*)g_W3t; uint4* d2 = (uint4*)(dyn + OFF_W3);
        for (int i = tid; i < 8 * 656 / 16; i += NT) d2[i] = s2[i];
    }
    if (tid < 320) sW1[tid] = W1[tid];
    if (tid < 64)  { sB1[tid] = B1[tid]; sB2[tid] = B2[tid]; }
    if (tid < 4)   sB3[tid] = B3[tid];

    // ---- Prim tile + rescale ----
    float mn = g_mn[row], mx = g_mx[row];
    float inv = 1.0f / fmaxf((mx - mn) * 0.5f, 1e-4f);
    if (tid < NY) {
        float v = Prim[(size_t)row * LROW + ((i0 + tid - 8) & LMASK)];
        sPrim[tid] = v;
        sY[tid] = (v - mn) * inv - 1.0f;
    }
    __syncthreads();

    // ---- conv1 + tanh -> sH1[j][ch] bf16 (j = 0..131) ----
    {
        const int cp = l;                 // channel pair
        const float b0 = sB1[2 * cp], b1v = sB1[2 * cp + 1];
        for (int j = w; j < N1; j += 16) {
            float a0 = b0, a1 = b1v;
            #pragma unroll
            for (int k = 0; k < 5; k++) {
                float yk = sY[j + k];
                float2 wv = *(const float2*)&sW1[k * 64 + 2 * cp];
                a0 += wv.x * yk;
                a1 += wv.y * yk;
            }
            uint32_t pr = pack_bf16x2(tanh_ap(a0), tanh_ap(a1));
            *(uint32_t*)(dyn + OFF_H1 + j * H_STRIDE + cp * 4) = pr;
        }
    }
    __syncthreads();

    // ---- conv2: D1[128,64] = A(H1 shifted) @ W2t^T via mma.sync ----
    {
        const int wm = w & 3, wn = w >> 2;
        const int r0 = wm * 32, c0 = wn * 16;
        const int ti = l >> 3, ii = l & 7;
        const int rA = ((ti & 1) ? 8 : 0) + ii;   // A lane row add
        const int cA = (ti & 2) ? 8 : 0;          // A lane col add
        float d[2][2][4];
        #pragma unroll
        for (int mi = 0; mi < 2; mi++)
            #pragma unroll
            for (int ni = 0; ni < 2; ni++)
                #pragma unroll
                for (int e = 0; e < 4; e++) d[mi][ni][e] = 0.f;

        for (int s = 0; s < 20; s++) {
            const int krow = s >> 2, kc = (s & 3) * 16;
            const int kabs = krow * 64 + kc;
            uint32_t a0f[4], a1f[4], bf[4];
            ldsm4(a0f, aH1 + (r0 +      krow + rA) * H_STRIDE + (kc + cA) * 2);
            ldsm4(a1f, aH1 + (r0 + 16 + krow + rA) * H_STRIDE + (kc + cA) * 2);
            ldsm4(bf, aW2 + (c0 + ((ti & 2) ? 8 : 0) + ii) * W_STRIDE
                          + (kabs + ((ti & 1) ? 8 : 0)) * 2);
            mma16816(d[0][0], a0f, bf + 0);
            mma16816(d[0][1], a0f, bf + 2);
            mma16816(d[1][0], a1f, bf + 0);
            mma16816(d[1][1], a1f, bf + 2);
        }

        // epilogue: +bias, tanh, pack -> sH2[point][ch] bf16
        const int g = l >> 2, l4 = l & 3;
        #pragma unroll
        for (int mi = 0; mi < 2; mi++) {
            #pragma unroll
            for (int ni = 0; ni < 2; ni++) {
                int rr = r0 + 16 * mi + g;
                int cc = c0 + 8 * ni + 2 * l4;
                float bb0 = sB2[cc], bb1 = sB2[cc + 1];
                uint32_t p0 = pack_bf16x2(tanh_ap(d[mi][ni][0] + bb0),
                                          tanh_ap(d[mi][ni][1] + bb1));
                uint32_t p1 = pack_bf16x2(tanh_ap(d[mi][ni][2] + bb0),
                                          tanh_ap(d[mi][ni][3] + bb1));
                *(uint32_t*)(dyn + OFF_H2 + rr * H_STRIDE + cc * 2) = p0;
                *(uint32_t*)(dyn + OFF_H2 + (rr + 8) * H_STRIDE + cc * 2) = p1;
            }
        }
    }
    __syncthreads();

    // ---- conv3: D2[128,8] = A(H2 shifted) @ W3t^T (warps 0..7) ----
    if (w < 8) {
        const int r0 = 16 * w;
        const int ti = l >> 3, ii = l & 7;
        const int rA = ((ti & 1) ? 8 : 0) + ii;
        const int cA = (ti & 2) ? 8 : 0;
        const int bi = l & 15;            // lanes for x2
        float dacc[4] = {0.f, 0.f, 0.f, 0.f};
        for (int s = 0; s < 20; s++) {
            const int krow = s >> 2, kc = (s & 3) * 16;
            const int kabs = krow * 64 + kc;
            uint32_t af[4], bf[2];
            ldsm4(af, aH2 + (r0 + krow + rA) * H_STRIDE + (kc + cA) * 2);
            ldsm2(bf, aW3 + (bi & 7) * W_STRIDE + (kabs + ((bi >> 3) ? 8 : 0)) * 2);
            mma16816(dacc, af, bf);
        }
        const int g = l >> 2, l4 = l & 3;
        if (l4 < 2) {
            int r = r0 + g;
            *(float2*)&sCoef[r * 4 + 2 * l4]       = make_float2(dacc[0], dacc[1]);
            *(float2*)&sCoef[(r + 8) * 4 + 2 * l4] = make_float2(dacc[2], dacc[3]);
        }
    }
    __syncthreads();

    // ---- coeffs -> alpha -> grad (warps 0..3) ----
    if (w < 4) {
        int r = w * 32 + l;               // coeff point p = r - 2
        float co0 = sCoef[r * 4 + 0] + sB3[0];
        float co1 = sCoef[r * 4 + 1] + sB3[1];
        float co2 = sCoef[r * 4 + 2] + sB3[2];
        float co3 = sCoef[r * 4 + 3] + sB3[3];
        float g = 0.f;
        #pragma unroll
        for (int k = 0; k < 5; k++) {
            float a = c_alpha_p[k] + co0 * c_nb[0][k] + co1 * c_nb[1][k]
                                   + co2 * c_nb[2][k] + co3 * c_nb[3][k];
            g += a * sPrim[r + 4 + k];    // Prim(p-2+k)
        }
        sGrad[r] = g * INVDX;             // sGrad[i] = grad(p = i-2)
    }
    __syncthreads();

    // ---- TVD flux + update ----
    if (tid < TLP && i0 + tid < LROW) {
        int t = tid;
        float g_m2 = sGrad[t], g_m1 = sGrad[t + 1], g_0 = sGrad[t + 2], g_p1 = sGrad[t + 3];
        float P_m1 = sPrim[t + 7], P_0 = sPrim[t + 8], P_p1 = sPrim[t + 9];

        float phim = phi_fn(g_m2, g_m1);
        float phi0 = phi_fn(g_m1, g_0);
        float phip = phi_fn(g_0,  g_p1);

        float uL1 = P_0  + 0.5f * DXC * phi0 * g_0;
        float uR1 = P_p1 - 0.5f * DXC * phip * g_p1;
        float f1  = 0.25f * (uL1 * uL1 + uR1 * uR1)
                  - 0.25f * fabsf(uL1 + uR1) * (uR1 - uL1);

        float uL0 = P_m1 + 0.5f * DXC * phim * g_m1;
        float uR0 = P_0  - 0.5f * DXC * phi0 * g_0;
        float f0  = 0.25f * (uL0 * uL0 + uR0 * uR0)
                  - 0.25f * fabsf(uL0 + uR0) * (uR0 - uL0);

        Out[(size_t)row * LROW + i0 + t] = P_0 - CFLC * (f1 - f0);
    }
}

// ================= launch =================
extern "C" void kernel_launch(void* const* d_in, const int* in_sizes, int n_in,
                              void* d_out, int out_size) {
    const float* Prim = (const float*)d_in[0];
    const float* W1   = (const float*)d_in[1];
    const float* B1   = (const float*)d_in[2];
    const float* W2   = (const float*)d_in[3];
    const float* B2   = (const float*)d_in[4];
    const float* W3   = (const float*)d_in[5];
    const float* B3   = (const float*)d_in[6];
    int Brows = in_sizes[0] / LROW;

    prep_weights<<<1, NT>>>(W2, W3);
    row_minmax<<<Brows, 256>>>(Prim);

    cudaFuncSetAttribute(fused_kernel,
                         cudaFuncAttributeMaxDynamicSharedMemorySize, DYN_BYTES);
    fused_kernel<<<dim3(NTILE, Brows), NT, DYN_BYTES>>>(
        Prim, W1, B1, B2, B3, (float*)d_out);
}